// round 17
// baseline (speedup 1.0000x reference)
#include <cuda_runtime.h>
#include <cuda_bf16.h>
#include <cstdint>

// out[b,p,h] = sum_{i,j} premise[b,p,i] * kernel[p,h,i,j] * hypothesis[b,h,j]
// B=8, P=96, H=96, D1=D2=128
//
// HBM-bound (604 MB K streamed once). One CTA per (p,h) (churn hides tile
// boundaries), 4-stage x 8 KB cp.async.bulk ring, per-chunk __syncthreads
// recycle (beats mbarrier empty-protocol), zero-pack f32x2 K operand.
//
// R17 change: the binding resource is smem wavefronts (1/cyc): per 512 B row
// TMA-write 4 + kv 4 + premise-broadcast 4 = 12 wf => DRAM capped ~79-82%,
// the measured plateau. Premise is now staged NON-duplicated (4 KB): 2
// broadcast LDS.128 + 8 alu dup-movs per row (alu has headroom) => 10 wf/row.
// The 4 KB saving also fits the 4-stage ring at 6 CTAs/SM (36992 B/CTA).

#define NB 8
#define NP 96
#define NH 96
#define ND 128

#define STAGES     4
#define NCHUNKS    8
#define CHUNK_B    8192          // 16 rows * 512 B
#define CHUNK_ROWS 16

#define BAR_OFF 0                // 4 mbarriers * 8 B
#define PRE_OFF 128              // 4 KB premise (non-dup)
#define K_OFF   (PRE_OFF + 4096) // 32 KB ring
#define SMEM_TOTAL (K_OFF + STAGES * CHUNK_B)   // 36992 B -> 6 CTAs/SM

using u64 = unsigned long long;

__device__ __forceinline__ u64 fma2(u64 a, u64 b, u64 c) {
    u64 d;
    asm("fma.rn.f32x2 %0, %1, %2, %3;" : "=l"(d) : "l"(a), "l"(b), "l"(c));
    return d;
}
__device__ __forceinline__ u64 dup2(float v) {
    u64 r;
    asm("mov.b64 %0, {%1, %1};" : "=l"(r) : "f"(v));
    return r;
}
__device__ __forceinline__ void unpack2(u64 v, float& lo, float& hi) {
    asm("mov.b64 {%0, %1}, %2;" : "=f"(lo), "=f"(hi) : "l"(v));
}
__device__ __forceinline__ uint32_t smem_u32(const void* p) {
    uint32_t a;
    asm("{ .reg .u64 t; cvta.to.shared.u64 t, %1; cvt.u32.u64 %0, t; }"
        : "=r"(a) : "l"(p));
    return a;
}
__device__ __forceinline__ void mbar_wait(uint32_t mbar, uint32_t parity) {
    asm volatile(
        "{\n\t"
        ".reg .pred P1;\n\t"
        "WL_%=:\n\t"
        "mbarrier.try_wait.parity.acquire.cta.shared::cta.b64 P1, [%0], %1, 0x989680;\n\t"
        "@P1 bra.uni WD_%=;\n\t"
        "bra.uni WL_%=;\n\t"
        "WD_%=:\n\t"
        "}"
        :: "r"(mbar), "r"(parity) : "memory");
}
__device__ __forceinline__ void issue_chunk(uint32_t bar, uint32_t dst,
                                            const unsigned char* src) {
    asm volatile("mbarrier.arrive.expect_tx.shared.b64 _, [%0], %1;"
                 :: "r"(bar), "r"(CHUNK_B) : "memory");
    asm volatile(
        "cp.async.bulk.shared::cluster.global.mbarrier::complete_tx::bytes "
        "[%0], [%1], %2, [%3];"
        :: "r"(dst), "l"(src), "r"(CHUNK_B), "r"(bar) : "memory");
}

__global__ void __launch_bounds__(128)
interaction_kernel(const float* __restrict__ premise,
                   const float* __restrict__ hyp,
                   const float* __restrict__ kern,
                   float* __restrict__ out)
{
    extern __shared__ __align__(128) unsigned char smem_raw[];

    const int h   = blockIdx.x;      // 0..95
    const int p   = blockIdx.y;      // 0..95
    const int tid = threadIdx.x;     // 0..127
    const int w   = tid >> 5;        // warp: rows ir ≡ w (mod 4) within chunk
    const int l   = tid & 31;        // lane: columns 4l..4l+3

    const uint32_t sbase = smem_u32(smem_raw);
    float* pre_s = reinterpret_cast<float*>(smem_raw + PRE_OFF);
    __shared__ float red[4][NB];

    const unsigned char* ksrc = reinterpret_cast<const unsigned char*>(
        kern + (((size_t)(p * NH + h)) << 14));

    // One mbarrier per stage (single expect_tx arrival per phase).
    if (tid == 0) {
#pragma unroll
        for (int s = 0; s < STAGES; s++)
            asm volatile("mbarrier.init.shared.b64 [%0], %1;"
                         :: "r"(sbase + BAR_OFF + 8 * s), "r"(1) : "memory");
    }
    __syncthreads();

    // Prologue: fill the ring (chunks 0..3 -> stages 0..3).
    if (tid == 0) {
#pragma unroll
        for (int s = 0; s < STAGES; s++)
            issue_chunk(sbase + BAR_OFF + 8 * s,
                        sbase + K_OFF + s * CHUNK_B,
                        ksrc + (size_t)s * CHUNK_B);
    }

    // Stage premise[:, p, :] NON-duplicated: pre_s[i*8 + b] = v  (4 KB)
#pragma unroll
    for (int r = 0; r < 8; r++) {
        int idx = tid + r * 128;          // 0..1023
        int i = idx >> 3;
        int b = idx & 7;
        pre_s[idx] = premise[((size_t)b * NP + p) * ND + i];
    }
    __syncthreads();

    const float4* pre4 = reinterpret_cast<const float4*>(pre_s);
    const ulonglong2* kbuf = reinterpret_cast<const ulonglong2*>(smem_raw + K_OFF);

    // acc[b][jp]: f32x2 accumulator for columns (4l+2jp, 4l+2jp+1), batch b
    u64 acc[NB][2];
#pragma unroll
    for (int b = 0; b < NB; b++) { acc[b][0] = 0ull; acc[b][1] = 0ull; }

#pragma unroll
    for (int c = 0; c < NCHUNKS; c++) {
        const int stage = c & (STAGES - 1);
        mbar_wait(sbase + BAR_OFF + 8 * stage, (c >= STAGES) ? 1u : 0u);

#pragma unroll
        for (int r = 0; r < CHUNK_ROWS / 4; r++) {
            const int ir = w + 4 * r;                 // row within chunk
            const int i  = c * CHUNK_ROWS + ir;       // row within tile
            ulonglong2 kv = kbuf[stage * 512 + ir * 32 + l];  // LDS.128
            float4 pv0 = pre4[i * 2 + 0];             // pre[i][0..3] broadcast
            float4 pv1 = pre4[i * 2 + 1];             // pre[i][4..7] broadcast
            u64 pr[NB] = { dup2(pv0.x), dup2(pv0.y), dup2(pv0.z), dup2(pv0.w),
                           dup2(pv1.x), dup2(pv1.y), dup2(pv1.z), dup2(pv1.w) };
#pragma unroll
            for (int b = 0; b < NB; b++) {
                acc[b][0] = fma2(kv.x, pr[b], acc[b][0]);
                acc[b][1] = fma2(kv.y, pr[b], acc[b][1]);
            }
        }

        // Recycle this stage for chunk c+4 (buffer-safe after the sync).
        if (c < NCHUNKS - STAGES) {
            __syncthreads();
            if (tid == 0)
                issue_chunk(sbase + BAR_OFF + 8 * stage,
                            sbase + K_OFF + stage * CHUNK_B,
                            ksrc + (size_t)(c + STAGES) * CHUNK_B);
        }
    }

    // Epilogue: fold hypothesis[b, h, 4l..4l+3] (float4 = two f32x2 pairs)
    float s[NB];
#pragma unroll
    for (int b = 0; b < NB; b++) {
        ulonglong2 hv = *reinterpret_cast<const ulonglong2*>(
            &hyp[((size_t)b * NH + h) * ND + 4 * l]);
        u64 t = fma2(acc[b][0], hv.x, 0ull);
        t = fma2(acc[b][1], hv.y, t);
        float lo, hi;
        unpack2(t, lo, hi);
        s[b] = lo + hi;
    }

    // Reduce over 32 lanes (j dimension)
#pragma unroll
    for (int off = 16; off; off >>= 1) {
#pragma unroll
        for (int b = 0; b < NB; b++)
            s[b] += __shfl_down_sync(0xffffffffu, s[b], off);
    }

    if (l == 0) {
#pragma unroll
        for (int b = 0; b < NB; b++) red[w][b] = s[b];
    }
    __syncthreads();

    if (tid < NB) {
        float v = red[0][tid] + red[1][tid] + red[2][tid] + red[3][tid];
        out[((size_t)tid * NP + p) * NH + h] = v;
    }
}

extern "C" void kernel_launch(void* const* d_in, const int* in_sizes, int n_in,
                              void* d_out, int out_size) {
    const float* premise = (const float*)d_in[0];  // (8, 96, 128)
    const float* hyp     = (const float*)d_in[1];  // (8, 96, 128)
    const float* kern    = (const float*)d_in[2];  // (96, 96, 128, 128)
    float* out = (float*)d_out;                    // (8, 96, 96)

    cudaFuncSetAttribute(interaction_kernel,
                         cudaFuncAttributeMaxDynamicSharedMemorySize, SMEM_TOTAL);
    dim3 grid(NH, NP);
    interaction_kernel<<<grid, 128, SMEM_TOTAL>>>(premise, hyp, kern, out);
}